// round 10
// baseline (speedup 1.0000x reference)
#include <cuda_runtime.h>
#include <cstdint>

// Problem constants
#define B_SZ   1024
#define F_SZ   784
#define OUT_F  1024
#define OR_T   32
#define AND_T  16
#define NLIT   1569              // 1 + 2*784 literals
#define NLIT_PAD 1572            // pad to multiple of 4 (16B rows for bulk copy)
#define NBG    32                // batch groups (32 batches each)

// Transposed literal table: g_Tt[bg][idx], row stride NLIT_PAD words.
__device__ __align__(16) uint32_t g_Tt[NBG * NLIT_PAD];

// ---------------------------------------------------------------------------
// Pack kernel: grid (25, 32), 128 threads. Coalesced 32x32 tile load ->
// smem transpose -> ballot per feature -> transposed table writes.
// ---------------------------------------------------------------------------
__global__ __launch_bounds__(128) void pack_kernel(const float* __restrict__ x) {
    __shared__ float tile[32][33];

    const int ft  = blockIdx.x;
    const int bg  = blockIdx.y;
    const int tid = threadIdx.x;
    const int f0  = ft * 32;

    const int c  = tid & 31;
    const int r0 = tid >> 5;
    #pragma unroll
    for (int r = r0; r < 32; r += 4) {
        const int f = f0 + c;
        tile[r][c] = (f < F_SZ) ? x[(size_t)(bg * 32 + r) * F_SZ + f] : 0.0f;
    }
    __syncthreads();

    uint32_t* trow = g_Tt + (size_t)bg * NLIT_PAD;
    const int lane = tid & 31;
    const int w    = tid >> 5;
    #pragma unroll
    for (int ff = w; ff < 32; ff += 4) {
        const int f = f0 + ff;
        if (f >= F_SZ) break;
        uint32_t m = __ballot_sync(0xFFFFFFFFu, tile[lane][ff] != 0.0f);
        if (lane == 0) {
            trow[1 + f]        = m;
            trow[1 + F_SZ + f] = ~m;
        }
    }
    if (ft == 0 && tid == 0) trow[0] = 0xFFFFFFFFu;   // const-true literal
}

// ---------------------------------------------------------------------------
// Logic kernel: grid (64 output-slices, 4 batch-slices) x 512 threads,
// 2 CTAs/SM. Each CTA: 16 outputs x 256 batches (8 batch-groups).
//  - Table slice = 8 rows x 6288B = 50KB via 8 linear bulk copies (4x smaller
//    fill than full-table replication); weights (32KB) staged concurrently.
//  - Warp = one output. Lane = (tg = lane>>3: term-of-quad, bg = lane&7).
//    8 quad-iterations cover the 32 OR-terms; OR-reduce across tg via shfl.
// ---------------------------------------------------------------------------
#define OPB 16                       // outputs per block
#define BGPB 8                       // batch-groups per block
#define NTHREADS 512
#define TSLICE_WORDS (BGPB * NLIT_PAD)          // 12576 words = 50304 B
#define CHUNK_BYTES  (NLIT_PAD * 4)             // 6288 B per bg row
#define W_WORDS (OPB * OR_T * AND_T)            // 8192 words = 32 KB
#define RES_WORDS (OPB * BGPB)                  // 128 words
#define MBAR_OFF_W (TSLICE_WORDS + W_WORDS + RES_WORDS)   // word offset (16B ok)
#define SMEM_BYTES ((MBAR_OFF_W + 4) * 4)

__global__ __launch_bounds__(NTHREADS) void logic_kernel(
    const int* __restrict__ weights, float* __restrict__ out) {

    extern __shared__ uint32_t smem[];
    uint32_t* sT   = smem;                      // table slice
    uint32_t* sw   = smem + TSLICE_WORDS;       // weights
    uint32_t* resb = sw + W_WORDS;              // results [out][bg]
    uint32_t  mbar_addr;
    {
        uint64_t* mb64 = (uint64_t*)(smem + MBAR_OFF_W);
        asm("{ .reg .u64 t; cvta.to.shared.u64 t, %1; cvt.u32.u64 %0, t; }"
            : "=r"(mbar_addr) : "l"((void*)mb64));
    }

    const int tid   = threadIdx.x;
    const int oBase = blockIdx.x * OPB;
    const int bg0   = blockIdx.y * BGPB;

    if (tid == 0) {
        asm volatile("mbarrier.init.shared.b64 [%0], 1;" :: "r"(mbar_addr) : "memory");
    }
    __syncthreads();

    if (tid == 0) {
        asm volatile("mbarrier.arrive.expect_tx.shared.b64 _, [%0], %1;"
                     :: "r"(mbar_addr), "r"((uint32_t)(BGPB * CHUNK_BYTES)) : "memory");
        const char* gsrc = (const char*)(g_Tt + (size_t)bg0 * NLIT_PAD);
        uint32_t sdst;
        asm("{ .reg .u64 t; cvta.to.shared.u64 t, %1; cvt.u32.u64 %0, t; }"
            : "=r"(sdst) : "l"((void*)sT));
        #pragma unroll
        for (int i = 0; i < BGPB; ++i) {
            asm volatile(
                "cp.async.bulk.shared::cta.global.mbarrier::complete_tx::bytes "
                "[%0], [%1], %2, [%3];"
                :: "r"(sdst + i * CHUNK_BYTES), "l"(gsrc + (size_t)i * CHUNK_BYTES),
                   "r"((uint32_t)CHUNK_BYTES), "r"(mbar_addr) : "memory");
        }
    }

    // Stage this block's weights while the DMA runs (4 uint4 per thread)
    {
        const uint4* wsrc = (const uint4*)(weights + (size_t)oBase * OR_T * AND_T);
        uint4* wdst = (uint4*)sw;
        #pragma unroll
        for (int i = 0; i < 4; ++i) wdst[tid + i * NTHREADS] = wsrc[tid + i * NTHREADS];
    }
    __syncthreads();

    // Wait for table slice DMA
    {
        uint32_t done;
        asm volatile(
            "{\n\t.reg .pred p;\n\t"
            "mbarrier.try_wait.parity.acquire.cta.shared::cta.b64 p, [%1], 0;\n\t"
            "selp.b32 %0, 1, 0, p;\n\t}"
            : "=r"(done) : "r"(mbar_addr) : "memory");
        if (!done) {
            asm volatile(
                "{\n\t.reg .pred P1;\n\t"
                "WL_%=:\n\t"
                "mbarrier.try_wait.parity.acquire.cta.shared::cta.b64 P1, [%0], 0, 0x989680;\n\t"
                "@P1 bra.uni WD_%=;\n\t"
                "bra.uni WL_%=;\n\t"
                "WD_%=:\n\t}"
                :: "r"(mbar_addr) : "memory");
        }
    }

    const int wid  = tid >> 5;               // 0..15: output within block
    const int lane = tid & 31;
    const int tg   = lane >> 3;              // term of quad (0..3)
    const int bg   = lane & 7;               // local batch-group (0..7)

    const uint32_t* swb  = sw + wid * (OR_T * AND_T);
    const uint32_t* trow = sT + bg * NLIT_PAD;

    uint32_t res = 0;
    #pragma unroll
    for (int t4 = 0; t4 < 8; ++t4) {
        const int term = t4 * 4 + tg;
        const uint4* tw4 = (const uint4*)(swb + term * AND_T);
        uint32_t m0 = ~0u, m1 = ~0u;
        uint32_t orw = 0;
        #pragma unroll
        for (int k4 = 0; k4 < 4; ++k4) {
            const uint4 w4 = tw4[k4];        // LDS.128, uniform per tg-group
            orw |= (w4.x | w4.y | w4.z | w4.w);
            m0 &= trow[w4.x];                // 4B gathers within this bg row
            m1 &= trow[w4.y];
            m0 &= trow[w4.z];
            m1 &= trow[w4.w];
        }
        const uint32_t sel = (orw != 0) ? ~0u : 0u;
        res |= (m0 & m1 & sel);
    }
    // OR-reduce across the 4 term-groups (lanes +-8, +-16 share bg)
    res |= __shfl_xor_sync(0xFFFFFFFFu, res, 8);
    res |= __shfl_xor_sync(0xFFFFFFFFu, res, 16);

    if (lane < 8) resb[wid * BGPB + bg] = res;
    __syncthreads();

    // Store: thread pair per batch; each thread writes 8 contiguous floats
    // (two float4). Batches bg0*32 .. bg0*32+255, outputs oBase .. oBase+15.
    {
        const int bloc = tid >> 1;           // local batch 0..255
        const int hf   = tid & 1;            // which 8-output half
        const int lbg  = bloc >> 5;          // local bg
        const int j    = bloc & 31;
        const int bglob = bg0 * 32 + bloc;
        float4 v0, v1;
        const int ob = hf * 8;
        #define GETBIT(ow) ((resb[(ob + (ow)) * BGPB + lbg] >> j) & 1u)
        v0.x = (float)GETBIT(0); v0.y = (float)GETBIT(1);
        v0.z = (float)GETBIT(2); v0.w = (float)GETBIT(3);
        v1.x = (float)GETBIT(4); v1.y = (float)GETBIT(5);
        v1.z = (float)GETBIT(6); v1.w = (float)GETBIT(7);
        #undef GETBIT
        float4* dst = (float4*)(out + (size_t)bglob * OUT_F + oBase + ob);
        dst[0] = v0;
        dst[1] = v1;
    }
}

// ---------------------------------------------------------------------------
extern "C" void kernel_launch(void* const* d_in, const int* in_sizes, int n_in,
                              void* d_out, int out_size) {
    const float* x       = (const float*)d_in[0];   // (1024, 784) float32
    const int*   weights = (const int*)d_in[1];     // (1024, 32, 16) int32
    float*       out     = (float*)d_out;           // (1024, 1024) float32

    cudaFuncSetAttribute(logic_kernel,
                         cudaFuncAttributeMaxDynamicSharedMemorySize, SMEM_BYTES);

    dim3 pgrid(25, 32);
    pack_kernel<<<pgrid, 128>>>(x);
    dim3 lgrid(OUT_F / OPB, NBG / BGPB);    // (64, 4) = 256 CTAs
    logic_kernel<<<lgrid, NTHREADS, SMEM_BYTES>>>(weights, out);
}